// round 10
// baseline (speedup 1.0000x reference)
#include <cuda_runtime.h>
#include <cuda_bf16.h>
#include <math.h>
#include <stdint.h>

#define NB 16
#define NT 2048
#define ND 256
#define NC 128
#define MAXK 20

typedef unsigned long long ull;

union U2 { float4 f4; ull u[2]; };

#define FMA2(acc, a, b) asm("fma.rn.f32x2 %0, %1, %2, %0;" : "+l"(acc) : "l"(a), "l"(b))
#define PACK2(d, x, y)  asm("mov.b64 %0, {%1, %2};" : "=l"(d) : "f"(x), "f"(y))
#define UNPACK2(x, y, d) asm("mov.b64 {%0, %1}, %2;" : "=f"(x), "=f"(y) : "l"(d))

// ---------- device scratch ----------
__device__ float g_E[NC * NC];        // exp(trans_lp) row-major, diag 0
__device__ float g_winit[NC];         // exp(init_lp)
__device__ float g_dtab[MAXK * NC];   // exp(len_lp[l-1][c])
__device__ float g_miT[ND * NC];      // (means*inv_var)^T  [d][c]
__device__ float g_cb[NC];            // const - 0.5*mq[c]
__device__ float g_iv[ND];            // 1/cov
__device__ float g_f[(size_t)NB * NT * NC]; // exp(emis - rowmax)
__device__ float g_mu[NB * NT];       // rowmax(emis)

// ---------- prep: 129 blocks x 128 ----------
__global__ void prep_kernel(const float* __restrict__ means,
                            const float* __restrict__ cov,
                            const float* __restrict__ trans,
                            const float* __restrict__ initlg,
                            const float* __restrict__ lograte) {
    const int c = threadIdx.x;
    const int lane = c & 31, wid = c >> 5;

    if (blockIdx.x < NC) {
        const int col = blockIdx.x;
        // miT column col: coalesced read of means row col, strided write
        {
            float iv0 = __fdividef(1.0f, cov[c]);
            float iv1 = __fdividef(1.0f, cov[c + 128]);
            if (col == 0) { g_iv[c] = iv0; g_iv[c + 128] = iv1; }
            g_miT[c * NC + col] = means[col * ND + c] * iv0;
            g_miT[(c + 128) * NC + col] = means[col * ND + c + 128] * iv1;
        }
        __shared__ float red[4];
        float v = (c == col) ? -1.0e9f : trans[c * NC + col];
        float mx = v;
#pragma unroll
        for (int o = 16; o >= 1; o >>= 1)
            mx = fmaxf(mx, __shfl_xor_sync(0xffffffffu, mx, o));
        if (lane == 0) red[wid] = mx;
        __syncthreads();
        mx = fmaxf(fmaxf(red[0], red[1]), fmaxf(red[2], red[3]));
        __syncthreads();
        float ex = (c == col) ? 0.0f : __expf(v - mx);
        float s = ex;
#pragma unroll
        for (int o = 16; o >= 1; o >>= 1)
            s += __shfl_xor_sync(0xffffffffu, s, o);
        if (lane == 0) red[wid] = s;
        __syncthreads();
        float tot = red[0] + red[1] + red[2] + red[3];
        g_E[c * NC + col] = __fdividef(ex, tot);
        return;
    }

    // block NC: cb, winit, dtab
    __shared__ float red2[4];
    __shared__ float shc;

    float lsum = 0.f;
    for (int d = c; d < ND; d += NC) lsum += __logf(cov[d]);
#pragma unroll
    for (int o = 16; o >= 1; o >>= 1)
        lsum += __shfl_xor_sync(0xffffffffu, lsum, o);
    if (lane == 0) red2[wid] = lsum;
    __syncthreads();
    if (c == 0)
        shc = -0.5f * (256.0f * 1.8378770664093453f +
                       red2[0] + red2[1] + red2[2] + red2[3]);
    __syncthreads();
    const float cst = shc;

    float mq = 0.f;
#pragma unroll 8
    for (int d = 0; d < ND; ++d) {
        float m = means[c * ND + d];
        mq = fmaf(m * m, __fdividef(1.0f, cov[d]), mq);
    }
    g_cb[c] = cst - 0.5f * mq;

    {
        float il = initlg[c];
        float mx = il;
#pragma unroll
        for (int o = 16; o >= 1; o >>= 1)
            mx = fmaxf(mx, __shfl_xor_sync(0xffffffffu, mx, o));
        __syncthreads();
        if (lane == 0) red2[wid] = mx;
        __syncthreads();
        mx = fmaxf(fmaxf(red2[0], red2[1]), fmaxf(red2[2], red2[3]));
        float ex = __expf(il - mx);
        float s = ex;
#pragma unroll
        for (int o = 16; o >= 1; o >>= 1)
            s += __shfl_xor_sync(0xffffffffu, s, o);
        __syncthreads();
        if (lane == 0) red2[wid] = s;
        __syncthreads();
        float tot = red2[0] + red2[1] + red2[2] + red2[3];
        g_winit[c] = __fdividef(ex, tot);
    }

    float r = lograte[c];
    float lam = __expf(r);
    float lg = 0.f;
    for (int l = 1; l <= MAXK; ++l) {
        lg += __logf((float)l);
        g_dtab[(l - 1) * NC + c] = __expf(fmaf((float)l, r, -lam) - lg);
    }
}

// ---------- emission GEMM + exp epilogue: 256 blocks x 256 ----------
__global__ __launch_bounds__(256) void emis_kernel(const float* __restrict__ feat) {
    __shared__ float A[128][40];
    __shared__ float Bt[32][132];
    __shared__ float ivs[32];

    const int tid = threadIdx.x;
    const int r0 = blockIdx.x * 128;
    const int cg = tid & 15;
    const int rr = tid >> 4;

    ull acc2[8][4];
#pragma unroll
    for (int i = 0; i < 8; ++i)
#pragma unroll
        for (int k = 0; k < 4; ++k) acc2[i][k] = 0ull;
    float xq[8];
#pragma unroll
    for (int i = 0; i < 8; ++i) xq[i] = 0.f;

    for (int d0 = 0; d0 < ND; d0 += 32) {
        __syncthreads();
#pragma unroll
        for (int k = 0; k < 4; ++k) {
            int i = tid + k * 256;
            int row = i >> 3, q = i & 7;
            *(float4*)&A[row][q * 4] = *(const float4*)&feat[(size_t)(r0 + row) * ND + d0 + q * 4];
        }
#pragma unroll
        for (int k = 0; k < 4; ++k) {
            int i = tid + k * 256;
            int drow = i >> 5, q = i & 31;
            *(float4*)&Bt[drow][q * 4] = *(const float4*)&g_miT[(size_t)(d0 + drow) * NC + q * 4];
        }
        if (tid < 32) ivs[tid] = g_iv[d0 + tid];
        __syncthreads();

#pragma unroll
        for (int u = 0; u < 2; ++u) {
            int dd = cg + u * 16;
            float iv = ivs[dd];
#pragma unroll
            for (int i = 0; i < 8; ++i) {
                float a = A[rr + 16 * i][dd];
                xq[i] = fmaf(a * iv, a, xq[i]);
            }
        }

#pragma unroll 8
        for (int dd = 0; dd < 32; ++dd) {
            U2 b0, b1;
            b0.f4 = *(const float4*)&Bt[dd][cg * 4];
            b1.f4 = *(const float4*)&Bt[dd][64 + cg * 4];
#pragma unroll
            for (int i = 0; i < 8; ++i) {
                float a = A[rr + 16 * i][dd];
                ull aa;
                PACK2(aa, a, a);
                FMA2(acc2[i][0], aa, b0.u[0]);
                FMA2(acc2[i][1], aa, b0.u[1]);
                FMA2(acc2[i][2], aa, b1.u[0]);
                FMA2(acc2[i][3], aa, b1.u[1]);
            }
        }
    }

#pragma unroll
    for (int o = 1; o < 16; o <<= 1) {
#pragma unroll
        for (int i = 0; i < 8; ++i)
            xq[i] += __shfl_xor_sync(0xffffffffu, xq[i], o, 16);
    }

    float cb[8];
    {
        float4 cb0 = *(const float4*)&g_cb[cg * 4];
        float4 cb1 = *(const float4*)&g_cb[64 + cg * 4];
        cb[0] = cb0.x; cb[1] = cb0.y; cb[2] = cb0.z; cb[3] = cb0.w;
        cb[4] = cb1.x; cb[5] = cb1.y; cb[6] = cb1.z; cb[7] = cb1.w;
    }
    const float L2E = 1.4426950408889634f;

#pragma unroll
    for (int i = 0; i < 8; ++i) {
        float hq = -0.5f * xq[i];
        float e[8], m = -3.0e38f;
#pragma unroll
        for (int k = 0; k < 4; ++k) {
            float lo, hi;
            UNPACK2(lo, hi, acc2[i][k]);
            e[k * 2] = lo + hq + cb[k * 2];
            e[k * 2 + 1] = hi + hq + cb[k * 2 + 1];
        }
#pragma unroll
        for (int k = 0; k < 8; ++k) m = fmaxf(m, e[k]);
#pragma unroll
        for (int off = 8; off >= 1; off >>= 1)
            m = fmaxf(m, __shfl_xor_sync(0xffffffffu, m, off, 16));
        float4 o0, o1;
        o0.x = exp2f((e[0] - m) * L2E); o0.y = exp2f((e[1] - m) * L2E);
        o0.z = exp2f((e[2] - m) * L2E); o0.w = exp2f((e[3] - m) * L2E);
        o1.x = exp2f((e[4] - m) * L2E); o1.y = exp2f((e[5] - m) * L2E);
        o1.z = exp2f((e[6] - m) * L2E); o1.w = exp2f((e[7] - m) * L2E);
        size_t row = (size_t)(r0 + rr + 16 * i);
        *(float4*)&g_f[row * NC + cg * 4] = o0;
        *(float4*)&g_f[row * NC + 64 + cg * 4] = o1;
        if (cg == 0) g_mu[row] = m;
    }
}

// ---------- recursion: 8 blocks x 256 = 2 independent batches/block ----------
// threads [0,128): batch 2*bid, threads [128,256): batch 2*bid+1.
// Named barriers (id 1 / id 2) keep the halves independent so each SMSP
// carries 2 warps of independent recursions -> latency hiding.
__global__ __launch_bounds__(256, 1) void rec_kernel(const int* __restrict__ lengths,
                                                     float* __restrict__ out) {
    const int tid = threadIdx.x;
    const int half = tid >> 7;          // 0 or 1
    const int c = tid & 127;            // channel
    const int b = blockIdx.x * 2 + half;
    const int w = (tid >> 5) & 3;       // warp-in-half
    const int lane = tid & 31;
    const int barid = half + 1;

    __shared__ __align__(16) float psh[2][2][NC];      // [half][parity][c]
    __shared__ __align__(16) unsigned shu[2][2][4];    // [half][parity][warp]
    __shared__ float shs[2][4];

    // full E row, packed pairs
    ull Er2[64];
#pragma unroll
    for (int k = 0; k < 32; ++k) {
        U2 u;
        u.f4 = *(const float4*)&g_E[c * NC + k * 4];
        Er2[k * 2] = u.u[0];
        Er2[k * 2 + 1] = u.u[1];
    }
    float Dr[MAXK];
#pragma unroll
    for (int j = 0; j < MAXK; ++j) Dr[j] = g_dtab[j * NC + c];
    float v[MAXK];
#pragma unroll
    for (int j = 0; j < MAXK; ++j) v[j] = 0.f;

    const int len = lengths[b];
    const float* fp = g_f + (size_t)b * NT * NC;
    const float* mup = g_mu + b * NT;

    float wv = g_winit[c];
    float fr_cur = __ldg(&fp[c]);           // f_0 * rm(=1)
    float al = fr_cur * (wv * Dr[0]);       // alpha_1 (window empty)
    float sigma = __ldg(&mup[0]);
    int ks = 0;
    float rm = 1.0f;
    int kcur = 0;
    float fA = __ldg(&fp[NC + c]),     muA = __ldg(&mup[1]);
    float fB = __ldg(&fp[2 * NC + c]), muB = __ldg(&mup[2]);

    for (int t = 1;; ++t) {
        const int par = t & 1;

        if (t == len) {
            float s = al;
#pragma unroll
            for (int o = 16; o >= 1; o >>= 1)
                s += __shfl_xor_sync(0xffffffffu, s, o);
            if (lane == 0) shs[half][w] = s;
            asm volatile("bar.sync %0, 128;" :: "r"(barid) : "memory");
            if (c == 0) {
                float st = (shs[half][0] + shs[half][1]) +
                           (shs[half][2] + shs[half][3]);
                out[b] = sigma + (float)ks * 0.6931471805599453f + logf(st);
            }
            break;
        }

        // publish alpha_t + warp max (single redux), one named barrier
        unsigned mu32;
        asm("redux.sync.max.u32 %0, %1, 0xffffffff;"
            : "=r"(mu32) : "r"(__float_as_uint(al)));
        if (lane == 0) shu[half][par][w] = mu32;
        psh[half][par][c] = al;
        asm volatile("bar.sync %0, 128;" :: "r"(barid) : "memory");

        // prefetch row t+2 (latency hidden under matvec)
        int tn = (t + 2 < NT) ? t + 2 : (NT - 1);
        float fN = __ldg(&fp[(size_t)tn * NC + c]);
        float muN = __ldg(&mup[tn]);

        // fresh normalizer from max(alpha_t), exponent only
        uint4 s0 = *(const uint4*)&shu[half][par][0];
        unsigned m01 = s0.x > s0.y ? s0.x : s0.y;
        unsigned m23 = s0.z > s0.w ? s0.z : s0.w;
        unsigned mm = m01 > m23 ? m01 : m23;
        unsigned e = mm >> 23;
        rm = __uint_as_float((254u - e) << 23);     // 2^(127-e)
        kcur = (int)e - 127;

        // window update with fr_cur; uses old wv
#pragma unroll
        for (int j = MAXK - 1; j >= 1; --j) v[j] = v[j - 1] * fr_cur;
        v[0] = wv * fr_cur;

        // duration dot for NEXT alpha (independent of new wv)
        float d0 = 0.f, d1 = 0.f, d2 = 0.f, d3 = 0.f;
#pragma unroll
        for (int j = 1; j < MAXK; j += 4) {
            d0 = fmaf(v[j - 1], Dr[j], d0);
            if (j + 1 < MAXK) d1 = fmaf(v[j], Dr[j + 1], d1);
            if (j + 2 < MAXK) d2 = fmaf(v[j + 1], Dr[j + 2], d2);
            if (j + 3 < MAXK) d3 = fmaf(v[j + 2], Dr[j + 3], d3);
        }
        float dsum = (d0 + d1) + (d2 + d3);

        // full-row matvec on unnormalized alpha
        const float* pb = &psh[half][par][0];
        ull a0 = 0ull, a1 = 0ull, a2 = 0ull, a3 = 0ull;
#pragma unroll
        for (int k = 0; k < 32; k += 2) {
            U2 p0, p1;
            p0.f4 = *(const float4*)&pb[k * 4];
            p1.f4 = *(const float4*)&pb[k * 4 + 4];
            FMA2(a0, Er2[k * 2], p0.u[0]);
            FMA2(a1, Er2[k * 2 + 1], p0.u[1]);
            FMA2(a2, Er2[k * 2 + 2], p1.u[0]);
            FMA2(a3, Er2[k * 2 + 3], p1.u[1]);
        }
        float x0, y0, x1, y1, x2, y2, x3, y3;
        UNPACK2(x0, y0, a0); UNPACK2(x1, y1, a1);
        UNPACK2(x2, y2, a2); UNPACK2(x3, y3, a3);
        wv = ((x0 + y0) + (x1 + y1)) + ((x2 + y2) + (x3 + y3));

        // next alpha: 2-op tail after wv
        fr_cur = fA * rm;
        al = fr_cur * fmaf(wv, Dr[0], dsum);
        sigma += muA;
        ks += kcur;

        fA = fB; muA = muB; fB = fN; muB = muN;
    }
}

extern "C" void kernel_launch(void* const* d_in, const int* in_sizes, int n_in,
                              void* d_out, int out_size) {
    const float* feat    = (const float*)d_in[0];
    const int*   lengths = (const int*)d_in[1];
    const float* means   = (const float*)d_in[2];
    const float* cov     = (const float*)d_in[3];
    const float* trans   = (const float*)d_in[4];
    const float* initlg  = (const float*)d_in[5];
    const float* lograte = (const float*)d_in[6];
    float* out = (float*)d_out;

    prep_kernel<<<NC + 1, 128>>>(means, cov, trans, initlg, lograte);
    emis_kernel<<<256, 256>>>(feat);
    rec_kernel<<<NB / 2, 256>>>(lengths, out);
}

// round 11
// speedup vs baseline: 1.2978x; 1.2978x over previous
#include <cuda_runtime.h>
#include <cuda_bf16.h>
#include <math.h>
#include <stdint.h>

#define NB 16
#define NT 2048
#define ND 256
#define NC 128
#define MAXK 20
#define WLEN 19   // live window elements

typedef unsigned long long ull;

union U2 { float4 f4; ull u[2]; };

#define FMA2(acc, a, b) asm("fma.rn.f32x2 %0, %1, %2, %0;" : "+l"(acc) : "l"(a), "l"(b))
#define PACK2(d, x, y)  asm("mov.b64 %0, {%1, %2};" : "=l"(d) : "f"(x), "f"(y))
#define UNPACK2(x, y, d) asm("mov.b64 {%0, %1}, %2;" : "=f"(x), "=f"(y) : "l"(d))

// ---------- device scratch ----------
__device__ float g_E[NC * NC];        // exp(trans_lp) row-major, diag 0
__device__ float g_winit[NC];         // exp(init_lp)
__device__ float g_dtab[MAXK * NC];   // exp(len_lp[l-1][c])
__device__ float g_miT[ND * NC];      // (means*inv_var)^T  [d][c]
__device__ float g_cb[NC];            // const - 0.5*mq[c]
__device__ float g_iv[ND];            // 1/cov
__device__ float g_f[(size_t)NB * NT * NC]; // exp(emis - rowmax)
__device__ float g_mu[NB * NT];       // rowmax(emis)

// ---------- prep_misc: 1 block x 256 : iv, cb, winit, dtab ----------
__global__ void prep_misc(const float* __restrict__ means,
                          const float* __restrict__ cov,
                          const float* __restrict__ initlg,
                          const float* __restrict__ lograte) {
    const int t = threadIdx.x;
    const int lane = t & 31, w = t >> 5;
    __shared__ float red[8];
    __shared__ float s_cst;
    __shared__ float s_iv[ND];

    // iv + logdet
    float cv = cov[t];
    float iv = __fdividef(1.0f, cv);
    g_iv[t] = iv;
    s_iv[t] = iv;
    float ls = __logf(cv);
#pragma unroll
    for (int o = 16; o >= 1; o >>= 1)
        ls += __shfl_xor_sync(0xffffffffu, ls, o);
    if (lane == 0) red[w] = ls;
    __syncthreads();
    if (t == 0) {
        float tot = 0.f;
        for (int i = 0; i < 8; ++i) tot += red[i];
        s_cst = -0.5f * (256.0f * 1.8378770664093453f + tot);
    }
    __syncthreads();
    const float cst = s_cst;

    // mq: warp w handles channels c = ci*8 + w
    for (int ci = 0; ci < 16; ++ci) {
        int c = ci * 8 + w;
        float p = 0.f;
#pragma unroll
        for (int k = 0; k < 8; ++k) {
            int d = k * 32 + lane;
            float m = means[c * ND + d];           // coalesced across lanes
            p = fmaf(m * m, s_iv[d], p);
        }
#pragma unroll
        for (int o = 16; o >= 1; o >>= 1)
            p += __shfl_xor_sync(0xffffffffu, p, o);
        if (lane == 0) g_cb[c] = cst - 0.5f * p;
    }

    if (t < NC) {
        // winit: softmax over 128 (4 warps participate; use smem reduce)
        float il = initlg[t];
        float mx = il;
#pragma unroll
        for (int o = 16; o >= 1; o >>= 1)
            mx = fmaxf(mx, __shfl_xor_sync(0xffffffffu, mx, o));
        if (lane == 0) red[w] = mx;
    }
    __syncthreads();
    if (t < NC) {
        float mx = fmaxf(fmaxf(red[0], red[1]), fmaxf(red[2], red[3]));
        float il = initlg[t];
        float ex = __expf(il - mx);
        float s = ex;
#pragma unroll
        for (int o = 16; o >= 1; o >>= 1)
            s += __shfl_xor_sync(0xffffffffu, s, o);
        if (lane == 0) red[4 + w] = s;
        __syncthreads();
        float tot = (red[4] + red[5]) + (red[6] + red[7]);
        g_winit[t] = __fdividef(ex, tot);

        // dtab
        float r = lograte[t];
        float lam = __expf(r);
        float lg = 0.f;
        for (int l = 1; l <= MAXK; ++l) {
            lg += __logf((float)l);
            g_dtab[(l - 1) * NC + t] = __expf(fmaf((float)l, r, -lam) - lg);
        }
    }
}

// ---------- prep_trans: 1 block x 1024 : E = exp(log_softmax(masked, axis=0)) ----------
__global__ __launch_bounds__(1024) void prep_trans(const float* __restrict__ trans) {
    const int t = threadIdx.x;
    const int j = t & 127;         // column
    const int g = t >> 7;          // row group 0..7 (16 rows each)
    __shared__ float gmax[8][NC];
    __shared__ float gsum[8][NC];
    __shared__ float colmax[NC], colinv[NC];

    float v[16];
    float mx = -3.0e38f;
#pragma unroll
    for (int k = 0; k < 16; ++k) {
        int i = g * 16 + k;
        float x = trans[i * NC + j];          // coalesced across j
        if (i == j) x = -1.0e9f;
        v[k] = x;
        mx = fmaxf(mx, x);
    }
    gmax[g][j] = mx;
    __syncthreads();
    if (t < NC) {
        float m = gmax[0][t];
#pragma unroll
        for (int i = 1; i < 8; ++i) m = fmaxf(m, gmax[i][t]);
        colmax[t] = m;
    }
    __syncthreads();
    float cm = colmax[j];
    float ex[16], s = 0.f;
#pragma unroll
    for (int k = 0; k < 16; ++k) {
        ex[k] = __expf(v[k] - cm);
        s += ex[k];
    }
    gsum[g][j] = s;
    __syncthreads();
    if (t < NC) {
        float ss = 0.f;
#pragma unroll
        for (int i = 0; i < 8; ++i) ss += gsum[i][t];
        colinv[t] = __fdividef(1.0f, ss);
    }
    __syncthreads();
    float inv = colinv[j];
#pragma unroll
    for (int k = 0; k < 16; ++k) {
        int i = g * 16 + k;
        g_E[i * NC + j] = (i == j) ? 0.0f : ex[k] * inv;   // coalesced
    }
}

// ---------- prep_miT: 32 blocks x 256 : transposed projected means ----------
__global__ void prep_miT(const float* __restrict__ means,
                         const float* __restrict__ cov) {
    __shared__ float tile[32][33];
    const int t = threadIdx.x;
    const int tc = blockIdx.x & 3, td = blockIdx.x >> 2;
    const int c0 = tc * 32, d0 = td * 32;
    const int r = t >> 5, dl = t & 31;

    float iv = __fdividef(1.0f, cov[d0 + dl]);
#pragma unroll
    for (int k = 0; k < 4; ++k) {
        int rr = r + 8 * k;
        tile[rr][dl] = means[(c0 + rr) * ND + d0 + dl] * iv;  // coalesced read
    }
    __syncthreads();
#pragma unroll
    for (int k = 0; k < 4; ++k) {
        int dr = r + 8 * k;
        g_miT[(d0 + dr) * NC + c0 + dl] = tile[dl][dr];       // coalesced write
    }
}

// ---------- emission GEMM + exp epilogue: 256 blocks x 256 ----------
__global__ __launch_bounds__(256) void emis_kernel(const float* __restrict__ feat) {
    __shared__ float A[128][40];
    __shared__ float Bt[32][132];
    __shared__ float ivs[32];

    const int tid = threadIdx.x;
    const int r0 = blockIdx.x * 128;
    const int cg = tid & 15;
    const int rr = tid >> 4;

    ull acc2[8][4];
#pragma unroll
    for (int i = 0; i < 8; ++i)
#pragma unroll
        for (int k = 0; k < 4; ++k) acc2[i][k] = 0ull;
    float xq[8];
#pragma unroll
    for (int i = 0; i < 8; ++i) xq[i] = 0.f;

    for (int d0 = 0; d0 < ND; d0 += 32) {
        __syncthreads();
#pragma unroll
        for (int k = 0; k < 4; ++k) {
            int i = tid + k * 256;
            int row = i >> 3, q = i & 7;
            *(float4*)&A[row][q * 4] = *(const float4*)&feat[(size_t)(r0 + row) * ND + d0 + q * 4];
        }
#pragma unroll
        for (int k = 0; k < 4; ++k) {
            int i = tid + k * 256;
            int drow = i >> 5, q = i & 31;
            *(float4*)&Bt[drow][q * 4] = *(const float4*)&g_miT[(size_t)(d0 + drow) * NC + q * 4];
        }
        if (tid < 32) ivs[tid] = g_iv[d0 + tid];
        __syncthreads();

#pragma unroll
        for (int u = 0; u < 2; ++u) {
            int dd = cg + u * 16;
            float iv = ivs[dd];
#pragma unroll
            for (int i = 0; i < 8; ++i) {
                float a = A[rr + 16 * i][dd];
                xq[i] = fmaf(a * iv, a, xq[i]);
            }
        }

#pragma unroll 8
        for (int dd = 0; dd < 32; ++dd) {
            U2 b0, b1;
            b0.f4 = *(const float4*)&Bt[dd][cg * 4];
            b1.f4 = *(const float4*)&Bt[dd][64 + cg * 4];
#pragma unroll
            for (int i = 0; i < 8; ++i) {
                float a = A[rr + 16 * i][dd];
                ull aa;
                PACK2(aa, a, a);
                FMA2(acc2[i][0], aa, b0.u[0]);
                FMA2(acc2[i][1], aa, b0.u[1]);
                FMA2(acc2[i][2], aa, b1.u[0]);
                FMA2(acc2[i][3], aa, b1.u[1]);
            }
        }
    }

#pragma unroll
    for (int o = 1; o < 16; o <<= 1) {
#pragma unroll
        for (int i = 0; i < 8; ++i)
            xq[i] += __shfl_xor_sync(0xffffffffu, xq[i], o, 16);
    }

    float cb[8];
    {
        float4 cb0 = *(const float4*)&g_cb[cg * 4];
        float4 cb1 = *(const float4*)&g_cb[64 + cg * 4];
        cb[0] = cb0.x; cb[1] = cb0.y; cb[2] = cb0.z; cb[3] = cb0.w;
        cb[4] = cb1.x; cb[5] = cb1.y; cb[6] = cb1.z; cb[7] = cb1.w;
    }
    const float L2E = 1.4426950408889634f;

#pragma unroll
    for (int i = 0; i < 8; ++i) {
        float hq = -0.5f * xq[i];
        float e[8], m = -3.0e38f;
#pragma unroll
        for (int k = 0; k < 4; ++k) {
            float lo, hi;
            UNPACK2(lo, hi, acc2[i][k]);
            e[k * 2] = lo + hq + cb[k * 2];
            e[k * 2 + 1] = hi + hq + cb[k * 2 + 1];
        }
#pragma unroll
        for (int k = 0; k < 8; ++k) m = fmaxf(m, e[k]);
#pragma unroll
        for (int off = 8; off >= 1; off >>= 1)
            m = fmaxf(m, __shfl_xor_sync(0xffffffffu, m, off, 16));
        float4 o0, o1;
        o0.x = exp2f((e[0] - m) * L2E); o0.y = exp2f((e[1] - m) * L2E);
        o0.z = exp2f((e[2] - m) * L2E); o0.w = exp2f((e[3] - m) * L2E);
        o1.x = exp2f((e[4] - m) * L2E); o1.y = exp2f((e[5] - m) * L2E);
        o1.z = exp2f((e[6] - m) * L2E); o1.w = exp2f((e[7] - m) * L2E);
        size_t row = (size_t)(r0 + rr + 16 * i);
        *(float4*)&g_f[row * NC + cg * 4] = o0;
        *(float4*)&g_f[row * NC + 64 + cg * 4] = o1;
        if (cg == 0) g_mu[row] = m;
    }
}

// ---------- recursion: 16 blocks x 128, one barrier, post-barrier max ----------
__global__ __launch_bounds__(128, 1) void rec_kernel(const int* __restrict__ lengths,
                                                     float* __restrict__ out) {
    const int b = blockIdx.x, c = threadIdx.x;
    const int w = c >> 5, lane = c & 31;
    __shared__ __align__(16) float psh[2][NC];
    __shared__ float shs[4];

    // full E row, packed pairs
    ull Er2[64];
#pragma unroll
    for (int k = 0; k < 32; ++k) {
        U2 u;
        u.f4 = *(const float4*)&g_E[c * NC + k * 4];
        Er2[k * 2] = u.u[0];
        Er2[k * 2 + 1] = u.u[1];
    }
    float Dr[MAXK];
#pragma unroll
    for (int j = 0; j < MAXK; ++j) Dr[j] = g_dtab[j * NC + c];
    float v[WLEN];
#pragma unroll
    for (int j = 0; j < WLEN; ++j) v[j] = 0.f;

    const int len = lengths[b];
    const float* fp = g_f + (size_t)b * NT * NC;
    const float* mup = g_mu + b * NT;

    float wv = g_winit[c];
    float fr_cur = __ldg(&fp[c]);           // f_0 * rm(=1)
    float al = fr_cur * (wv * Dr[0]);       // alpha_1 (window empty)
    float sigma = __ldg(&mup[0]);
    int ks = 0;
    float rm = 1.0f;
    int kcur = 0;
    float fA = __ldg(&fp[NC + c]),     muA = __ldg(&mup[1]);
    float fB = __ldg(&fp[2 * NC + c]), muB = __ldg(&mup[2]);

    for (int t = 1;; ++t) {
        const int par = t & 1;

        if (t == len) {
            float s = al;
#pragma unroll
            for (int o = 16; o >= 1; o >>= 1)
                s += __shfl_xor_sync(0xffffffffu, s, o);
            if (lane == 0) shs[w] = s;
            __syncthreads();
            if (c == 0) {
                float st = (shs[0] + shs[1]) + (shs[2] + shs[3]);
                out[b] = sigma + (float)ks * 0.6931471805599453f + logf(st);
            }
            break;
        }

        // minimal pre-barrier chain: publish alpha, barrier
        psh[par][c] = al;
        __syncthreads();

        // prefetch row t+2 (latency hidden under matvec)
        int tn = (t + 2 < NT) ? t + 2 : (NT - 1);
        float fN = __ldg(&fp[(size_t)tn * NC + c]);
        float muN = __ldg(&mup[tn]);

        // block max of alpha_t from psh, computed per-warp in matvec shadow:
        // lane reads psh[4*lane..+3] (covers all 128), 3 vmax + one redux
        {
            const uint4* pu = (const uint4*)&psh[par][0];
            uint4 q = pu[lane];
            unsigned q01 = q.x > q.y ? q.x : q.y;
            unsigned q23 = q.z > q.w ? q.z : q.w;
            unsigned qm = q01 > q23 ? q01 : q23;
            unsigned mm;
            asm("redux.sync.max.u32 %0, %1, 0xffffffff;" : "=r"(mm) : "r"(qm));
            unsigned e = mm >> 23;
            rm = __uint_as_float((254u - e) << 23);     // 2^(127-e)
            kcur = (int)e - 127;
        }

        // window update with fr_cur; uses old wv (19 live elements)
#pragma unroll
        for (int j = WLEN - 1; j >= 1; --j) v[j] = v[j - 1] * fr_cur;
        v[0] = wv * fr_cur;

        // duration dot for NEXT alpha (independent of new wv)
        float d0 = 0.f, d1 = 0.f, d2 = 0.f, d3 = 0.f;
#pragma unroll
        for (int j = 1; j < MAXK; j += 4) {
            d0 = fmaf(v[j - 1], Dr[j], d0);
            if (j + 1 < MAXK) d1 = fmaf(v[j], Dr[j + 1], d1);
            if (j + 2 < MAXK) d2 = fmaf(v[j + 1], Dr[j + 2], d2);
            if (j + 3 < MAXK) d3 = fmaf(v[j + 2], Dr[j + 3], d3);
        }
        float dsum = (d0 + d1) + (d2 + d3);

        // full-row matvec on unnormalized alpha
        const float* pb = &psh[par][0];
        ull a0 = 0ull, a1 = 0ull, a2 = 0ull, a3 = 0ull;
#pragma unroll
        for (int k = 0; k < 32; k += 2) {
            U2 p0, p1;
            p0.f4 = *(const float4*)&pb[k * 4];
            p1.f4 = *(const float4*)&pb[k * 4 + 4];
            FMA2(a0, Er2[k * 2], p0.u[0]);
            FMA2(a1, Er2[k * 2 + 1], p0.u[1]);
            FMA2(a2, Er2[k * 2 + 2], p1.u[0]);
            FMA2(a3, Er2[k * 2 + 3], p1.u[1]);
        }
        float x0, y0, x1, y1, x2, y2, x3, y3;
        UNPACK2(x0, y0, a0); UNPACK2(x1, y1, a1);
        UNPACK2(x2, y2, a2); UNPACK2(x3, y3, a3);
        wv = ((x0 + y0) + (x1 + y1)) + ((x2 + y2) + (x3 + y3));

        // next alpha: 2-op tail after wv
        fr_cur = fA * rm;
        al = fr_cur * fmaf(wv, Dr[0], dsum);
        sigma += muA;
        ks += kcur;

        fA = fB; muA = muB; fB = fN; muB = muN;
    }
}

extern "C" void kernel_launch(void* const* d_in, const int* in_sizes, int n_in,
                              void* d_out, int out_size) {
    const float* feat    = (const float*)d_in[0];
    const int*   lengths = (const int*)d_in[1];
    const float* means   = (const float*)d_in[2];
    const float* cov     = (const float*)d_in[3];
    const float* trans   = (const float*)d_in[4];
    const float* initlg  = (const float*)d_in[5];
    const float* lograte = (const float*)d_in[6];
    float* out = (float*)d_out;

    prep_misc<<<1, 256>>>(means, cov, initlg, lograte);
    prep_trans<<<1, 1024>>>(trans);
    prep_miT<<<32, 256>>>(means, cov);
    emis_kernel<<<256, 256>>>(feat);
    rec_kernel<<<NB, 128>>>(lengths, out);
}